// round 1
// baseline (speedup 1.0000x reference)
#include <cuda_runtime.h>

#define BB  2
#define LL  1024
#define DD  768
#define HH  12
#define DHD 64
#define BHN (BB*HH)

// ---- scratch (device globals: allowed; no runtime allocation) ----
__device__ float g_q [BHN*LL*DHD];         //  6.3 MB  [bh][l][dh]
__device__ float g_k [BHN*LL*DHD];
__device__ float g_v [BHN*LL*DHD];
__device__ float g_qw[5*BHN*LL*DHD];       // 31.5 MB  [i][bh][l][dh]
__device__ float g_s [(size_t)BHN*LL*LL];  // 100.7 MB [bh][l][r]

// ============================================================
// K1: QKV projection GEMM. out = hidden @ W + b, scattered to
// head-major [b,h,l,dh]. Tile 128x128, 256 thr, 8x8 microtile.
// ============================================================
__global__ __launch_bounds__(256) void qkv_kernel(
    const float* __restrict__ hidden,
    const float* __restrict__ Wq, const float* __restrict__ bq,
    const float* __restrict__ Wk, const float* __restrict__ bk,
    const float* __restrict__ Wv, const float* __restrict__ bv)
{
    __shared__ float As[16*132];   // A transposed: As[kk][m]
    __shared__ float Bs[16*128];   // Bs[kk][n]

    const int mat = blockIdx.z;
    const float* W    = (mat==0) ? Wq : (mat==1 ? Wk : Wv);
    const float* bias = (mat==0) ? bq : (mat==1 ? bk : bv);
    float* outp       = (mat==0) ? g_q : (mat==1 ? g_k : g_v);

    const int n0 = blockIdx.x * 128;
    const int m0 = blockIdx.y * 128;
    const int tid = threadIdx.x;
    const int ty = tid >> 4, tx = tid & 15;

    float acc[8][8];
    #pragma unroll
    for (int i = 0; i < 8; i++)
        #pragma unroll
        for (int j = 0; j < 8; j++) acc[i][j] = 0.f;

    for (int kc0 = 0; kc0 < DD; kc0 += 16) {
        #pragma unroll
        for (int it = 0; it < 2; it++) {
            int idx = tid + it*256;          // 512 float4
            int m = idx >> 2, kq = idx & 3;
            float4 a = *(const float4*)&hidden[(m0+m)*DD + kc0 + kq*4];
            As[(kq*4+0)*132 + m] = a.x;
            As[(kq*4+1)*132 + m] = a.y;
            As[(kq*4+2)*132 + m] = a.z;
            As[(kq*4+3)*132 + m] = a.w;
        }
        #pragma unroll
        for (int it = 0; it < 2; it++) {
            int idx = tid + it*256;          // 512 float4
            int kk = idx >> 5, nq = idx & 31;
            float4 w = *(const float4*)&W[(kc0+kk)*DD + n0 + nq*4];
            *(float4*)&Bs[kk*128 + nq*4] = w;
        }
        __syncthreads();
        #pragma unroll
        for (int kk = 0; kk < 16; kk++) {
            float4 a0 = *(const float4*)&As[kk*132 + ty*8];
            float4 a1 = *(const float4*)&As[kk*132 + ty*8 + 4];
            float4 b0 = *(const float4*)&Bs[kk*128 + tx*8];
            float4 b1 = *(const float4*)&Bs[kk*128 + tx*8 + 4];
            float ra[8] = {a0.x,a0.y,a0.z,a0.w,a1.x,a1.y,a1.z,a1.w};
            float rb[8] = {b0.x,b0.y,b0.z,b0.w,b1.x,b1.y,b1.z,b1.w};
            #pragma unroll
            for (int i = 0; i < 8; i++)
                #pragma unroll
                for (int j = 0; j < 8; j++)
                    acc[i][j] += ra[i]*rb[j];
        }
        __syncthreads();
    }

    #pragma unroll
    for (int i = 0; i < 8; i++) {
        int rg = m0 + ty*8 + i;
        int b  = rg >> 10, l = rg & 1023;
        #pragma unroll
        for (int jq = 0; jq < 2; jq++) {
            int cg = n0 + tx*8 + jq*4;
            int h  = cg >> 6, dh = cg & 63;
            float4 v;
            v.x = acc[i][jq*4+0] + __ldg(&bias[cg+0]);
            v.y = acc[i][jq*4+1] + __ldg(&bias[cg+1]);
            v.z = acc[i][jq*4+2] + __ldg(&bias[cg+2]);
            v.w = acc[i][jq*4+3] + __ldg(&bias[cg+3]);
            *(float4*)&outp[((b*HH + h)*LL + l)*DHD + dh] = v;
        }
    }
}

// ============================================================
// K1b: qw[i][bh][l][e] = sum_d q[bh][l][d] * ssan_w[i][h][d][e]
// Tile 128(l) x 64(e), 256 thr, 8x4 microtile. K=64.
// dynamic smem = (64*132 + 64*64)*4 = 50176 B
// ============================================================
__global__ __launch_bounds__(256) void qw_kernel(const float* __restrict__ ssw)
{
    extern __shared__ float sm[];
    float* Qs = sm;            // [64][132] (transposed: Qs[d][m])
    float* Ws = sm + 64*132;   // [64][64]

    const int i5 = blockIdx.z;
    const int bh = blockIdx.y;
    const int h  = bh % HH;
    const int m0 = blockIdx.x * 128;
    const int tid = threadIdx.x;
    const int ty = tid >> 4, tx = tid & 15;

    const float* qb = g_q + (bh*LL + m0)*DHD;
    #pragma unroll
    for (int it = 0; it < 8; it++) {
        int idx = tid + it*256;         // 2048 float4
        int m = idx >> 4, dq = idx & 15;
        float4 a = *(const float4*)&qb[m*DHD + dq*4];
        Qs[(dq*4+0)*132 + m] = a.x;
        Qs[(dq*4+1)*132 + m] = a.y;
        Qs[(dq*4+2)*132 + m] = a.z;
        Qs[(dq*4+3)*132 + m] = a.w;
    }
    const float* wb = ssw + (i5*HH + h)*DHD*DHD;
    #pragma unroll
    for (int it = 0; it < 4; it++) {
        int idx = tid + it*256;         // 1024 float4
        *(float4*)&Ws[idx*4] = *(const float4*)&wb[idx*4];
    }
    __syncthreads();

    float acc[8][4];
    #pragma unroll
    for (int i = 0; i < 8; i++)
        #pragma unroll
        for (int j = 0; j < 4; j++) acc[i][j] = 0.f;

    #pragma unroll 8
    for (int d = 0; d < 64; d++) {
        float4 q0 = *(const float4*)&Qs[d*132 + ty*8];
        float4 q1 = *(const float4*)&Qs[d*132 + ty*8 + 4];
        float4 w  = *(const float4*)&Ws[d*64 + tx*4];
        float rq[8] = {q0.x,q0.y,q0.z,q0.w,q1.x,q1.y,q1.z,q1.w};
        float rw[4] = {w.x,w.y,w.z,w.w};
        #pragma unroll
        for (int i = 0; i < 8; i++)
            #pragma unroll
            for (int j = 0; j < 4; j++)
                acc[i][j] += rq[i]*rw[j];
    }

    float* ob = g_qw + ((i5*BHN + bh)*LL + m0)*DHD;
    #pragma unroll
    for (int i = 0; i < 8; i++) {
        float4 v; v.x = acc[i][0]; v.y = acc[i][1]; v.z = acc[i][2]; v.w = acc[i][3];
        *(float4*)&ob[(ty*8+i)*DHD + tx*4] = v;
    }
}

// ============================================================
// K2: fused score tile kernel. 128x128 tile per CTA, 8x8 micro.
//   scores = (q@k^T + q@E_band + k@E_band)/8 + mask
//          + sum_i (qw_i @ k^T + ab_i) * struct_i
// dynamic smem = (2*64*132 + 64*260)*4 = 134144 B
// ============================================================
__global__ __launch_bounds__(256) void scores_kernel(
    const float* __restrict__ mask,
    const float* __restrict__ structm,
    const float* __restrict__ dist,
    const float* __restrict__ abv)
{
    extern __shared__ float sm[];
    float* Qs = sm;              // [64][132] transposed (also reused for qw tiles)
    float* Ks = sm + 8448;       // [64][132] transposed
    float* Es = sm + 16896;      // [64][260] transposed band: Es[d][j]

    const int kt = blockIdx.x, qt = blockIdx.y, bh = blockIdx.z;
    const int b = bh / HH, h = bh % HH;
    const int tid = threadIdx.x;
    const int ty = tid >> 4, tx = tid & 15;
    const int m0 = qt*128, n0 = kt*128;

    const float* qb = g_q + (bh*LL + m0)*DHD;
    const float* kb = g_k + (bh*LL + n0)*DHD;
    #pragma unroll
    for (int it = 0; it < 8; it++) {
        int idx = tid + it*256;
        int m = idx >> 4, dq = idx & 15;
        float4 a = *(const float4*)&qb[m*DHD + dq*4];
        Qs[(dq*4+0)*132+m]=a.x; Qs[(dq*4+1)*132+m]=a.y;
        Qs[(dq*4+2)*132+m]=a.z; Qs[(dq*4+3)*132+m]=a.w;
        float4 c = *(const float4*)&kb[m*DHD + dq*4];
        Ks[(dq*4+0)*132+m]=c.x; Ks[(dq*4+1)*132+m]=c.y;
        Ks[(dq*4+2)*132+m]=c.z; Ks[(dq*4+3)*132+m]=c.w;
    }
    // dist_emb band: rows [base, base+254], base = (qt-kt)*128 + 896, all in [0,2046]
    const int base = (qt - kt)*128 + 896;
    for (int idx = tid; idx < 255*16; idx += 256) {
        int j = idx >> 4, dq = idx & 15;
        float4 a = *(const float4*)&dist[(base + j)*DHD + dq*4];
        Es[(dq*4+0)*260+j]=a.x; Es[(dq*4+1)*260+j]=a.y;
        Es[(dq*4+2)*260+j]=a.z; Es[(dq*4+3)*260+j]=a.w;
    }
    __syncthreads();

    float acc[8][8];
    #pragma unroll
    for (int i = 0; i < 8; i++)
        #pragma unroll
        for (int j = 0; j < 8; j++) acc[i][j] = 0.f;

    const int e0 = ty*8 - tx*8 + 120;   // multiple of 8, in [0,240]
    #pragma unroll 4
    for (int d = 0; d < 64; d++) {
        float4 q0 = *(const float4*)&Qs[d*132 + ty*8];
        float4 q1 = *(const float4*)&Qs[d*132 + ty*8 + 4];
        float4 k0 = *(const float4*)&Ks[d*132 + tx*8];
        float4 k1 = *(const float4*)&Ks[d*132 + tx*8 + 4];
        float4 e0v = *(const float4*)&Es[d*260 + e0];
        float4 e1v = *(const float4*)&Es[d*260 + e0 + 4];
        float4 e2v = *(const float4*)&Es[d*260 + e0 + 8];
        float4 e3v = *(const float4*)&Es[d*260 + e0 + 12];
        float rq[8] = {q0.x,q0.y,q0.z,q0.w,q1.x,q1.y,q1.z,q1.w};
        float rk[8] = {k0.x,k0.y,k0.z,k0.w,k1.x,k1.y,k1.z,k1.w};
        float re[16] = {e0v.x,e0v.y,e0v.z,e0v.w, e1v.x,e1v.y,e1v.z,e1v.w,
                        e2v.x,e2v.y,e2v.z,e2v.w, e3v.x,e3v.y,e3v.z,e3v.w};
        #pragma unroll
        for (int i = 0; i < 8; i++)
            #pragma unroll
            for (int j = 0; j < 8; j++) {
                float ee = re[i - j + 7];   // E[(m-n)+1023] row, d-th element
                acc[i][j] += rq[i]*rk[j];
                acc[i][j] += rq[i]*ee;
                acc[i][j] += rk[j]*ee;
            }
    }

    const int rowg = m0 + ty*8;
    const int colg = n0 + tx*8;
    #pragma unroll
    for (int i = 0; i < 8; i++)
        #pragma unroll
        for (int j = 0; j < 8; j++)
            acc[i][j] = acc[i][j]*0.125f + __ldg(&mask[b*LL + colg + j]);

    // 5 bilinear structure terms (NOT scaled by 1/8)
    for (int i5 = 0; i5 < 5; i5++) {
        __syncthreads();
        const float* qwb = g_qw + ((i5*BHN + bh)*LL + m0)*DHD;
        #pragma unroll
        for (int it = 0; it < 8; it++) {
            int idx = tid + it*256;
            int m = idx >> 4, dq = idx & 15;
            float4 a = *(const float4*)&qwb[m*DHD + dq*4];
            Qs[(dq*4+0)*132+m]=a.x; Qs[(dq*4+1)*132+m]=a.y;
            Qs[(dq*4+2)*132+m]=a.z; Qs[(dq*4+3)*132+m]=a.w;
        }
        __syncthreads();

        float bacc[8][8];
        #pragma unroll
        for (int i = 0; i < 8; i++)
            #pragma unroll
            for (int j = 0; j < 8; j++) bacc[i][j] = 0.f;

        #pragma unroll 4
        for (int d = 0; d < 64; d++) {
            float4 q0 = *(const float4*)&Qs[d*132 + ty*8];
            float4 q1 = *(const float4*)&Qs[d*132 + ty*8 + 4];
            float4 k0 = *(const float4*)&Ks[d*132 + tx*8];
            float4 k1 = *(const float4*)&Ks[d*132 + tx*8 + 4];
            float rq[8] = {q0.x,q0.y,q0.z,q0.w,q1.x,q1.y,q1.z,q1.w};
            float rk[8] = {k0.x,k0.y,k0.z,k0.w,k1.x,k1.y,k1.z,k1.w};
            #pragma unroll
            for (int i = 0; i < 8; i++)
                #pragma unroll
                for (int j = 0; j < 8; j++)
                    bacc[i][j] += rq[i]*rk[j];
        }
        float ab = __ldg(&abv[i5*HH + h]);
        const float* st = structm + ((size_t)(i5*BB + b)*LL + rowg)*LL + colg;
        #pragma unroll
        for (int i = 0; i < 8; i++)
            #pragma unroll
            for (int j = 0; j < 8; j++)
                acc[i][j] += (bacc[i][j] + ab) * __ldg(&st[i*LL + j]);
    }

    float* sp = g_s + ((size_t)bh*LL + rowg)*LL + colg;
    #pragma unroll
    for (int i = 0; i < 8; i++) {
        float4 v0; v0.x=acc[i][0]; v0.y=acc[i][1]; v0.z=acc[i][2]; v0.w=acc[i][3];
        float4 v1; v1.x=acc[i][4]; v1.y=acc[i][5]; v1.z=acc[i][6]; v1.w=acc[i][7];
        *(float4*)&sp[(size_t)i*LL]     = v0;
        *(float4*)&sp[(size_t)i*LL + 4] = v1;
    }
}

// ============================================================
// K3: softmax over each of BH*L rows (len 1024). One warp/row.
// ============================================================
__global__ __launch_bounds__(256) void softmax_kernel()
{
    const int warp = threadIdx.x >> 5, lane = threadIdx.x & 31;
    const size_t row = (size_t)blockIdx.x * 8 + warp;
    float* rp = g_s + row * LL;

    float4 v[8];
    float mx = -1e30f;
    #pragma unroll
    for (int k2 = 0; k2 < 8; k2++) {
        v[k2] = *(const float4*)&rp[(lane + k2*32)*4];
        mx = fmaxf(mx, fmaxf(fmaxf(v[k2].x, v[k2].y), fmaxf(v[k2].z, v[k2].w)));
    }
    #pragma unroll
    for (int o = 16; o > 0; o >>= 1) mx = fmaxf(mx, __shfl_xor_sync(0xffffffffu, mx, o));

    float s = 0.f;
    #pragma unroll
    for (int k2 = 0; k2 < 8; k2++) {
        v[k2].x = __expf(v[k2].x - mx);
        v[k2].y = __expf(v[k2].y - mx);
        v[k2].z = __expf(v[k2].z - mx);
        v[k2].w = __expf(v[k2].w - mx);
        s += v[k2].x + v[k2].y + v[k2].z + v[k2].w;
    }
    #pragma unroll
    for (int o = 16; o > 0; o >>= 1) s += __shfl_xor_sync(0xffffffffu, s, o);

    const float inv = 1.f / s;
    #pragma unroll
    for (int k2 = 0; k2 < 8; k2++) {
        v[k2].x *= inv; v[k2].y *= inv; v[k2].z *= inv; v[k2].w *= inv;
        *(float4*)&rp[(lane + k2*32)*4] = v[k2];
    }
}

// ============================================================
// K4: ctx = probs @ v, per (b,h). Tile 128(l) x 64(dh), K=1024
// in 32-chunks. Output [b, l, h*64+dh].
// ============================================================
__global__ __launch_bounds__(256) void pv_kernel(float* __restrict__ out)
{
    __shared__ float Ps[32*132];  // transposed Ps[kk][m]
    __shared__ float Vs[32*64];

    const int bh = blockIdx.y;
    const int b = bh / HH, h = bh % HH;
    const int m0 = blockIdx.x * 128;
    const int tid = threadIdx.x;
    const int ty = tid >> 4, tx = tid & 15;

    const float* pb = g_s + (size_t)bh*LL*LL;
    const float* vb = g_v + (size_t)bh*LL*DHD;

    float acc[8][4];
    #pragma unroll
    for (int i = 0; i < 8; i++)
        #pragma unroll
        for (int j = 0; j < 4; j++) acc[i][j] = 0.f;

    for (int kc0 = 0; kc0 < LL; kc0 += 32) {
        #pragma unroll
        for (int it = 0; it < 4; it++) {
            int idx = tid + it*256;          // 1024 float4
            int m = idx >> 3, kq = idx & 7;
            float4 a = *(const float4*)&pb[(size_t)(m0+m)*LL + kc0 + kq*4];
            Ps[(kq*4+0)*132+m]=a.x; Ps[(kq*4+1)*132+m]=a.y;
            Ps[(kq*4+2)*132+m]=a.z; Ps[(kq*4+3)*132+m]=a.w;
        }
        #pragma unroll
        for (int it = 0; it < 2; it++) {
            int idx = tid + it*256;          // 512 float4
            *(float4*)&Vs[idx*4] = *(const float4*)&vb[(size_t)kc0*DHD + idx*4];
        }
        __syncthreads();
        #pragma unroll
        for (int kk = 0; kk < 32; kk++) {
            float4 p0 = *(const float4*)&Ps[kk*132 + ty*8];
            float4 p1 = *(const float4*)&Ps[kk*132 + ty*8 + 4];
            float4 vv = *(const float4*)&Vs[kk*64 + tx*4];
            float rp[8] = {p0.x,p0.y,p0.z,p0.w,p1.x,p1.y,p1.z,p1.w};
            float rv[4] = {vv.x,vv.y,vv.z,vv.w};
            #pragma unroll
            for (int i = 0; i < 8; i++)
                #pragma unroll
                for (int j = 0; j < 4; j++)
                    acc[i][j] += rp[i]*rv[j];
        }
        __syncthreads();
    }

    #pragma unroll
    for (int i = 0; i < 8; i++) {
        int l = m0 + ty*8 + i;
        float4 v; v.x=acc[i][0]; v.y=acc[i][1]; v.z=acc[i][2]; v.w=acc[i][3];
        *(float4*)&out[((size_t)b*LL + l)*DD + h*DHD + tx*4] = v;
    }
}

// ============================================================
extern "C" void kernel_launch(void* const* d_in, const int* in_sizes, int n_in,
                              void* d_out, int out_size)
{
    const float* hidden  = (const float*)d_in[0];
    const float* mask    = (const float*)d_in[1];
    const float* structm = (const float*)d_in[2];
    const float* Wq      = (const float*)d_in[3];
    const float* bq      = (const float*)d_in[4];
    const float* Wk      = (const float*)d_in[5];
    const float* bk      = (const float*)d_in[6];
    const float* Wv      = (const float*)d_in[7];
    const float* bv      = (const float*)d_in[8];
    const float* dist    = (const float*)d_in[9];
    const float* ssw     = (const float*)d_in[10];
    const float* abv     = (const float*)d_in[11];
    float* out = (float*)d_out;

    // opt-in smem (idempotent host-side attribute set; not a stream op)
    cudaFuncSetAttribute(qw_kernel,     cudaFuncAttributeMaxDynamicSharedMemorySize, 50176);
    cudaFuncSetAttribute(scores_kernel, cudaFuncAttributeMaxDynamicSharedMemorySize, 134144);

    qkv_kernel   <<<dim3(6,16,3),  256>>>(hidden, Wq,bq, Wk,bk, Wv,bv);
    qw_kernel    <<<dim3(8,24,5),  256, 50176>>>(ssw);
    scores_kernel<<<dim3(8,8,24),  256, 134144>>>(mask, structm, dist, abv);
    softmax_kernel<<<3072,         256>>>();
    pv_kernel    <<<dim3(8,24),    256>>>(out);
}

// round 2
// speedup vs baseline: 1.4600x; 1.4600x over previous
#include <cuda_runtime.h>

#define BB  2
#define LL  1024
#define DD  768
#define HH  12
#define DHD 64
#define BHN (BB*HH)

// ---- scratch (device globals: allowed; no runtime allocation) ----
__device__ float g_q [BHN*LL*DHD];         //  6.3 MB  [bh][l][dh]
__device__ float g_k [BHN*LL*DHD];
__device__ float g_v [BHN*LL*DHD];
__device__ float g_qw[5*BHN*LL*DHD];       // 31.5 MB  [i][bh][l][dh]
__device__ float g_s [(size_t)BHN*LL*LL];  // 100.7 MB [bh][l][r]

// ============================================================
// tf32 helpers
// ============================================================
__device__ __forceinline__ unsigned f2tf(float x) {
    unsigned u; asm("cvt.rna.tf32.f32 %0, %1;" : "=r"(u) : "f"(x)); return u;
}

__device__ __forceinline__ void mma8(float* c, const uint4 a, const uint2 b) {
    asm volatile(
        "mma.sync.aligned.m16n8k8.row.col.f32.tf32.tf32.f32 "
        "{%0,%1,%2,%3}, {%4,%5,%6,%7}, {%8,%9}, {%0,%1,%2,%3};"
        : "+f"(c[0]), "+f"(c[1]), "+f"(c[2]), "+f"(c[3])
        : "r"(a.x), "r"(a.y), "r"(a.z), "r"(a.w), "r"(b.x), "r"(b.y));
}

// Stage a 128x64 row-major fp32 tile into A-fragment-major tf32 SMEM.
// Layout: Af[ks(8)][mt(8)][lane(32)][4 regs]  -> 8192 u32 = 32KB
__device__ __forceinline__ void stageA(unsigned* dst, const float* __restrict__ src, int tid) {
    #pragma unroll
    for (int it = 0; it < 8; it++) {
        int idx = tid + it*256;
        int m = idx >> 4, k4 = idx & 15;
        float4 v = *(const float4*)(src + m*64 + k4*4);
        int mt = m >> 4, r = m & 15;
        int rbit = (r >> 3) & 1;
        int laneb = (r & 7) << 2;
        float vv[4] = {v.x, v.y, v.z, v.w};
        #pragma unroll
        for (int c2 = 0; c2 < 4; c2++) {
            int k  = k4*4 + c2;
            int ks = k >> 3, cc = k & 3, hf = (k >> 2) & 1;
            dst[((ks*8 + mt)*32 + (laneb | cc))*4 + (rbit + hf*2)] = f2tf(vv[c2]);
        }
    }
}

// Stage a 128x64 row-major fp32 tile into B-fragment-major tf32 SMEM.
// Layout: Bf[ks(8)][nt(16)][lane(32)][2 regs] -> 8192 u32 = 32KB
// Rows n >= nvalid are zero-filled.
__device__ __forceinline__ void stageB(unsigned* dst, const float* __restrict__ src,
                                       int tid, int nvalid) {
    #pragma unroll
    for (int it = 0; it < 8; it++) {
        int idx = tid + it*256;
        int n = idx >> 4, k4 = idx & 15;
        float4 v = make_float4(0.f, 0.f, 0.f, 0.f);
        if (n < nvalid) v = *(const float4*)(src + n*64 + k4*4);
        int nt = n >> 3;
        int laneb = (n & 7) << 2;
        float vv[4] = {v.x, v.y, v.z, v.w};
        #pragma unroll
        for (int c2 = 0; c2 < 4; c2++) {
            int k  = k4*4 + c2;
            int ks = k >> 3, cc = k & 3, hf = (k >> 2) & 1;
            dst[((ks*16 + nt)*32 + (laneb | cc))*2 + hf] = f2tf(vv[c2]);
        }
    }
}

// One 128x128x64 GEMM pass: warp tile 32x64 (warp grid 4m x 2n).
__device__ __forceinline__ void gemm64(const unsigned* __restrict__ Af,
                                       const unsigned* __restrict__ Bf,
                                       int wm, int wn, int lane, float bacc[2][8][4]) {
    #pragma unroll
    for (int ks = 0; ks < 8; ks++) {
        uint4 a0 = *(const uint4*)(Af + ((ks*8 + wm*2 + 0)*32 + lane)*4);
        uint4 a1 = *(const uint4*)(Af + ((ks*8 + wm*2 + 1)*32 + lane)*4);
        #pragma unroll
        for (int j = 0; j < 8; j++) {
            uint2 b = *(const uint2*)(Bf + ((ks*16 + wn*8 + j)*32 + lane)*2);
            mma8(bacc[0][j], a0, b);
            mma8(bacc[1][j], a1, b);
        }
    }
}

__device__ __forceinline__ void zeroacc(float a[2][8][4]) {
    #pragma unroll
    for (int i = 0; i < 2; i++)
        #pragma unroll
        for (int j = 0; j < 8; j++)
            #pragma unroll
            for (int c = 0; c < 4; c++) a[i][j][c] = 0.f;
}

// Write bacc (c-fragment layout) into QEbuf[128][132] fp32.
__device__ __forceinline__ void writeQE(float* buf, const float bacc[2][8][4],
                                        int wm, int wn, int lane) {
    int r0 = wm*32 + (lane >> 2);
    int c0 = wn*64 + (lane & 3)*2;
    #pragma unroll
    for (int i = 0; i < 2; i++)
        #pragma unroll
        for (int j = 0; j < 8; j++) {
            int rr = r0 + i*16, cc = c0 + j*8;
            *(float2*)(buf + rr*132 + cc)      = make_float2(bacc[i][j][0], bacc[i][j][1]);
            *(float2*)(buf + (rr+8)*132 + cc)  = make_float2(bacc[i][j][2], bacc[i][j][3]);
        }
}

// Gather diagonal contributions: scores[R,C] += buf[rowsel][j], j = R-C+127-half*128.
// useCol=false -> rowsel=R (QE term), useCol=true -> rowsel=C (KE term).
__device__ __forceinline__ void gatherDiag(const float* __restrict__ buf, float acc[2][8][4],
                                           int wm, int wn, int lane, int half, bool useCol) {
    int r0 = wm*32 + (lane >> 2);
    int c0 = wn*64 + (lane & 3)*2;
    int off = 127 - half*128;
    #pragma unroll
    for (int i = 0; i < 2; i++)
        #pragma unroll
        for (int j = 0; j < 8; j++) {
            int rr = r0 + i*16, cc = c0 + j*8;
            #pragma unroll
            for (int c2 = 0; c2 < 4; c2++) {
                int R = rr + (c2 >> 1)*8;
                int C = cc + (c2 & 1);
                int J = R - C + off;
                if ((unsigned)J < 128u) {
                    int rowi = useCol ? C : R;
                    acc[i][j][c2] += buf[rowi*132 + J];
                }
            }
        }
}

// ============================================================
// K1: QKV projection GEMM (fp32 CUDA cores, unchanged).
// ============================================================
__global__ __launch_bounds__(256) void qkv_kernel(
    const float* __restrict__ hidden,
    const float* __restrict__ Wq, const float* __restrict__ bq,
    const float* __restrict__ Wk, const float* __restrict__ bk,
    const float* __restrict__ Wv, const float* __restrict__ bv)
{
    __shared__ float As[16*132];
    __shared__ float Bs[16*128];

    const int mat = blockIdx.z;
    const float* W    = (mat==0) ? Wq : (mat==1 ? Wk : Wv);
    const float* bias = (mat==0) ? bq : (mat==1 ? bk : bv);
    float* outp       = (mat==0) ? g_q : (mat==1 ? g_k : g_v);

    const int n0 = blockIdx.x * 128;
    const int m0 = blockIdx.y * 128;
    const int tid = threadIdx.x;
    const int ty = tid >> 4, tx = tid & 15;

    float acc[8][8];
    #pragma unroll
    for (int i = 0; i < 8; i++)
        #pragma unroll
        for (int j = 0; j < 8; j++) acc[i][j] = 0.f;

    for (int kc0 = 0; kc0 < DD; kc0 += 16) {
        #pragma unroll
        for (int it = 0; it < 2; it++) {
            int idx = tid + it*256;
            int m = idx >> 2, kq = idx & 3;
            float4 a = *(const float4*)&hidden[(m0+m)*DD + kc0 + kq*4];
            As[(kq*4+0)*132 + m] = a.x;
            As[(kq*4+1)*132 + m] = a.y;
            As[(kq*4+2)*132 + m] = a.z;
            As[(kq*4+3)*132 + m] = a.w;
        }
        #pragma unroll
        for (int it = 0; it < 2; it++) {
            int idx = tid + it*256;
            int kk = idx >> 5, nq = idx & 31;
            float4 w = *(const float4*)&W[(kc0+kk)*DD + n0 + nq*4];
            *(float4*)&Bs[kk*128 + nq*4] = w;
        }
        __syncthreads();
        #pragma unroll
        for (int kk = 0; kk < 16; kk++) {
            float4 a0 = *(const float4*)&As[kk*132 + ty*8];
            float4 a1 = *(const float4*)&As[kk*132 + ty*8 + 4];
            float4 b0 = *(const float4*)&Bs[kk*128 + tx*8];
            float4 b1 = *(const float4*)&Bs[kk*128 + tx*8 + 4];
            float ra[8] = {a0.x,a0.y,a0.z,a0.w,a1.x,a1.y,a1.z,a1.w};
            float rb[8] = {b0.x,b0.y,b0.z,b0.w,b1.x,b1.y,b1.z,b1.w};
            #pragma unroll
            for (int i = 0; i < 8; i++)
                #pragma unroll
                for (int j = 0; j < 8; j++)
                    acc[i][j] += ra[i]*rb[j];
        }
        __syncthreads();
    }

    #pragma unroll
    for (int i = 0; i < 8; i++) {
        int rg = m0 + ty*8 + i;
        int b  = rg >> 10, l = rg & 1023;
        #pragma unroll
        for (int jq = 0; jq < 2; jq++) {
            int cg = n0 + tx*8 + jq*4;
            int h  = cg >> 6, dh = cg & 63;
            float4 v;
            v.x = acc[i][jq*4+0] + __ldg(&bias[cg+0]);
            v.y = acc[i][jq*4+1] + __ldg(&bias[cg+1]);
            v.z = acc[i][jq*4+2] + __ldg(&bias[cg+2]);
            v.w = acc[i][jq*4+3] + __ldg(&bias[cg+3]);
            *(float4*)&outp[((b*HH + h)*LL + l)*DHD + dh] = v;
        }
    }
}

// ============================================================
// K1b: qw precompute (fp32 CUDA cores, unchanged).
// ============================================================
__global__ __launch_bounds__(256) void qw_kernel(const float* __restrict__ ssw)
{
    extern __shared__ float sm[];
    float* Qs = sm;
    float* Ws = sm + 64*132;

    const int i5 = blockIdx.z;
    const int bh = blockIdx.y;
    const int h  = bh % HH;
    const int m0 = blockIdx.x * 128;
    const int tid = threadIdx.x;
    const int ty = tid >> 4, tx = tid & 15;

    const float* qb = g_q + (bh*LL + m0)*DHD;
    #pragma unroll
    for (int it = 0; it < 8; it++) {
        int idx = tid + it*256;
        int m = idx >> 4, dq = idx & 15;
        float4 a = *(const float4*)&qb[m*DHD + dq*4];
        Qs[(dq*4+0)*132 + m] = a.x;
        Qs[(dq*4+1)*132 + m] = a.y;
        Qs[(dq*4+2)*132 + m] = a.z;
        Qs[(dq*4+3)*132 + m] = a.w;
    }
    const float* wb = ssw + (i5*HH + h)*DHD*DHD;
    #pragma unroll
    for (int it = 0; it < 4; it++) {
        int idx = tid + it*256;
        *(float4*)&Ws[idx*4] = *(const float4*)&wb[idx*4];
    }
    __syncthreads();

    float acc[8][4];
    #pragma unroll
    for (int i = 0; i < 8; i++)
        #pragma unroll
        for (int j = 0; j < 4; j++) acc[i][j] = 0.f;

    #pragma unroll 8
    for (int d = 0; d < 64; d++) {
        float4 q0 = *(const float4*)&Qs[d*132 + ty*8];
        float4 q1 = *(const float4*)&Qs[d*132 + ty*8 + 4];
        float4 w  = *(const float4*)&Ws[d*64 + tx*4];
        float rq[8] = {q0.x,q0.y,q0.z,q0.w,q1.x,q1.y,q1.z,q1.w};
        float rw[4] = {w.x,w.y,w.z,w.w};
        #pragma unroll
        for (int i = 0; i < 8; i++)
            #pragma unroll
            for (int j = 0; j < 4; j++)
                acc[i][j] += rq[i]*rw[j];
    }

    float* ob = g_qw + ((i5*BHN + bh)*LL + m0)*DHD;
    #pragma unroll
    for (int i = 0; i < 8; i++) {
        float4 v; v.x = acc[i][0]; v.y = acc[i][1]; v.z = acc[i][2]; v.w = acc[i][3];
        *(float4*)&ob[(ty*8+i)*DHD + tx*4] = v;
    }
}

// ============================================================
// K2: fused score kernel on tensor cores (tf32 mma.sync).
// Per CTA: 128x128 score tile. 256 threads = 8 warps (4m x 2n).
// Computes: (q@k^T + q-pos + k-pos)/8 + mask + sum_i (qw_i@k^T + ab_i)*struct_i
// SMEM: Af 32K | KfB 32K | KaA 32K | Ef 32K | QEbuf 128x132 f32 (67.6K)
// ============================================================
#define SMEM_SCORES (49664*4)

__global__ __launch_bounds__(256, 1) void scores_kernel(
    const float* __restrict__ mask,
    const float* __restrict__ structm,
    const float* __restrict__ dist,
    const float* __restrict__ abv)
{
    extern __shared__ unsigned smu[];
    unsigned* Af   = smu;
    unsigned* KfB  = smu + 8192;
    unsigned* KaA  = smu + 16384;
    unsigned* Ef   = smu + 24576;
    float*    QEb  = (float*)(smu + 32768);   // 128*132 floats

    const int bh = blockIdx.x, kt = blockIdx.y, qt = blockIdx.z;
    const int b = bh / HH, h = bh % HH;
    const int m0 = qt*128, n0 = kt*128;
    const int tid = threadIdx.x, lane = tid & 31, wid = tid >> 5;
    const int wm = wid & 3, wn = wid >> 2;

    const float* qtile = g_q + (bh*LL + m0)*DHD;
    const float* ktile = g_k + (bh*LL + n0)*DHD;

    stageA(Af, qtile, tid);
    stageB(KfB, ktile, tid, 128);
    stageA(KaA, ktile, tid);
    const int base = (qt - kt)*128 + 896;        // dist row of local diag j=0
    stageB(Ef, dist + (size_t)base*DHD, tid, 128);
    __syncthreads();

    float acc[2][8][4];
    float bacc[2][8][4];
    zeroacc(acc);

    // ---- positional terms, half 0 (j in [0,128)) ----
    zeroacc(bacc);
    gemm64(Af, Ef, wm, wn, lane, bacc);          // QE = q @ E^T
    writeQE(QEb, bacc, wm, wn, lane);
    __syncthreads();
    gatherDiag(QEb, acc, wm, wn, lane, 0, false);
    __syncthreads();

    zeroacc(bacc);
    gemm64(KaA, Ef, wm, wn, lane, bacc);         // KE = k @ E^T
    writeQE(QEb, bacc, wm, wn, lane);
    __syncthreads();
    gatherDiag(QEb, acc, wm, wn, lane, 0, true);
    __syncthreads();

    // ---- positional terms, half 1 (j in [128,255)) ----
    {
        int nv = 1919 - base; if (nv > 128) nv = 128;
        stageB(Ef, dist + (size_t)(base + 128)*DHD, tid, nv);
    }
    __syncthreads();

    zeroacc(bacc);
    gemm64(Af, Ef, wm, wn, lane, bacc);
    writeQE(QEb, bacc, wm, wn, lane);
    __syncthreads();
    gatherDiag(QEb, acc, wm, wn, lane, 1, false);
    __syncthreads();

    zeroacc(bacc);
    gemm64(KaA, Ef, wm, wn, lane, bacc);
    writeQE(QEb, bacc, wm, wn, lane);
    __syncthreads();
    gatherDiag(QEb, acc, wm, wn, lane, 1, true);

    // ---- q @ k^T, then scale + mask ----
    zeroacc(bacc);
    gemm64(Af, KfB, wm, wn, lane, bacc);

    const float* mrow = mask + b*LL + n0;
    const int c0col = wn*64 + (lane & 3)*2;
    #pragma unroll
    for (int j = 0; j < 8; j++) {
        float2 mk = *(const float2*)(mrow + c0col + j*8);
        #pragma unroll
        for (int i = 0; i < 2; i++) {
            acc[i][j][0] = (acc[i][j][0] + bacc[i][j][0])*0.125f + mk.x;
            acc[i][j][1] = (acc[i][j][1] + bacc[i][j][1])*0.125f + mk.y;
            acc[i][j][2] = (acc[i][j][2] + bacc[i][j][2])*0.125f + mk.x;
            acc[i][j][3] = (acc[i][j][3] + bacc[i][j][3])*0.125f + mk.y;
        }
    }

    // ---- 5 bilinear structure passes ----
    const int r0 = wm*32 + (lane >> 2);
    for (int i5 = 0; i5 < 5; i5++) {
        __syncthreads();
        stageA(Af, g_qw + (((size_t)i5*BHN + bh)*LL + m0)*DHD, tid);
        __syncthreads();
        zeroacc(bacc);
        gemm64(Af, KfB, wm, wn, lane, bacc);

        float ab = __ldg(&abv[i5*HH + h]);
        const float* stb = structm + (((size_t)(i5*BB + b)*LL + m0)*LL) + n0;
        #pragma unroll
        for (int i = 0; i < 2; i++)
            #pragma unroll
            for (int j = 0; j < 8; j++) {
                int rr = r0 + i*16, cc = c0col + j*8;
                float2 s0 = *(const float2*)(stb + (size_t)rr*LL + cc);
                float2 s1 = *(const float2*)(stb + (size_t)(rr+8)*LL + cc);
                acc[i][j][0] += (bacc[i][j][0] + ab)*s0.x;
                acc[i][j][1] += (bacc[i][j][1] + ab)*s0.y;
                acc[i][j][2] += (bacc[i][j][2] + ab)*s1.x;
                acc[i][j][3] += (bacc[i][j][3] + ab)*s1.y;
            }
    }

    // ---- write scores ----
    float* sp = g_s + ((size_t)bh*LL + m0)*LL + n0;
    #pragma unroll
    for (int i = 0; i < 2; i++)
        #pragma unroll
        for (int j = 0; j < 8; j++) {
            int rr = r0 + i*16, cc = c0col + j*8;
            *(float2*)(sp + (size_t)rr*LL + cc)     = make_float2(acc[i][j][0], acc[i][j][1]);
            *(float2*)(sp + (size_t)(rr+8)*LL + cc) = make_float2(acc[i][j][2], acc[i][j][3]);
        }
}

// ============================================================
// K3: softmax (unchanged).
// ============================================================
__global__ __launch_bounds__(256) void softmax_kernel()
{
    const int warp = threadIdx.x >> 5, lane = threadIdx.x & 31;
    const size_t row = (size_t)blockIdx.x * 8 + warp;
    float* rp = g_s + row * LL;

    float4 v[8];
    float mx = -1e30f;
    #pragma unroll
    for (int k2 = 0; k2 < 8; k2++) {
        v[k2] = *(const float4*)&rp[(lane + k2*32)*4];
        mx = fmaxf(mx, fmaxf(fmaxf(v[k2].x, v[k2].y), fmaxf(v[k2].z, v[k2].w)));
    }
    #pragma unroll
    for (int o = 16; o > 0; o >>= 1) mx = fmaxf(mx, __shfl_xor_sync(0xffffffffu, mx, o));

    float s = 0.f;
    #pragma unroll
    for (int k2 = 0; k2 < 8; k2++) {
        v[k2].x = __expf(v[k2].x - mx);
        v[k2].y = __expf(v[k2].y - mx);
        v[k2].z = __expf(v[k2].z - mx);
        v[k2].w = __expf(v[k2].w - mx);
        s += v[k2].x + v[k2].y + v[k2].z + v[k2].w;
    }
    #pragma unroll
    for (int o = 16; o > 0; o >>= 1) s += __shfl_xor_sync(0xffffffffu, s, o);

    const float inv = 1.f / s;
    #pragma unroll
    for (int k2 = 0; k2 < 8; k2++) {
        v[k2].x *= inv; v[k2].y *= inv; v[k2].z *= inv; v[k2].w *= inv;
        *(float4*)&rp[(lane + k2*32)*4] = v[k2];
    }
}

// ============================================================
// K4: ctx = probs @ v (unchanged).
// ============================================================
__global__ __launch_bounds__(256) void pv_kernel(float* __restrict__ out)
{
    __shared__ float Ps[32*132];
    __shared__ float Vs[32*64];

    const int bh = blockIdx.y;
    const int b = bh / HH, h = bh % HH;
    const int m0 = blockIdx.x * 128;
    const int tid = threadIdx.x;
    const int ty = tid >> 4, tx = tid & 15;

    const float* pb = g_s + (size_t)bh*LL*LL;
    const float* vb = g_v + (size_t)bh*LL*DHD;

    float acc[8][4];
    #pragma unroll
    for (int i = 0; i < 8; i++)
        #pragma unroll
        for (int j = 0; j < 4; j++) acc[i][j] = 0.f;

    for (int kc0 = 0; kc0 < LL; kc0 += 32) {
        #pragma unroll
        for (int it = 0; it < 4; it++) {
            int idx = tid + it*256;
            int m = idx >> 3, kq = idx & 7;
            float4 a = *(const float4*)&pb[(size_t)(m0+m)*LL + kc0 + kq*4];
            Ps[(kq*4+0)*132+m]=a.x; Ps[(kq*4+1)*132+m]=a.y;
            Ps[(kq*4+2)*132+m]=a.z; Ps[(kq*4+3)*132+m]=a.w;
        }
        #pragma unroll
        for (int it = 0; it < 2; it++) {
            int idx = tid + it*256;
            *(float4*)&Vs[idx*4] = *(const float4*)&vb[(size_t)kc0*DHD + idx*4];
        }
        __syncthreads();
        #pragma unroll
        for (int kk = 0; kk < 32; kk++) {
            float4 p0 = *(const float4*)&Ps[kk*132 + ty*8];
            float4 p1 = *(const float4*)&Ps[kk*132 + ty*8 + 4];
            float4 vv = *(const float4*)&Vs[kk*64 + tx*4];
            float rp[8] = {p0.x,p0.y,p0.z,p0.w,p1.x,p1.y,p1.z,p1.w};
            float rv[4] = {vv.x,vv.y,vv.z,vv.w};
            #pragma unroll
            for (int i = 0; i < 8; i++)
                #pragma unroll
                for (int j = 0; j < 4; j++)
                    acc[i][j] += rp[i]*rv[j];
        }
        __syncthreads();
    }

    #pragma unroll
    for (int i = 0; i < 8; i++) {
        int l = m0 + ty*8 + i;
        float4 v; v.x=acc[i][0]; v.y=acc[i][1]; v.z=acc[i][2]; v.w=acc[i][3];
        *(float4*)&out[((size_t)b*LL + l)*DD + h*DHD + tx*4] = v;
    }
}

// ============================================================
extern "C" void kernel_launch(void* const* d_in, const int* in_sizes, int n_in,
                              void* d_out, int out_size)
{
    const float* hidden  = (const float*)d_in[0];
    const float* mask    = (const float*)d_in[1];
    const float* structm = (const float*)d_in[2];
    const float* Wq      = (const float*)d_in[3];
    const float* bq      = (const float*)d_in[4];
    const float* Wk      = (const float*)d_in[5];
    const float* bk      = (const float*)d_in[6];
    const float* Wv      = (const float*)d_in[7];
    const float* bv      = (const float*)d_in[8];
    const float* dist    = (const float*)d_in[9];
    const float* ssw     = (const float*)d_in[10];
    const float* abv     = (const float*)d_in[11];
    float* out = (float*)d_out;

    cudaFuncSetAttribute(qw_kernel,     cudaFuncAttributeMaxDynamicSharedMemorySize, 50176);
    cudaFuncSetAttribute(scores_kernel, cudaFuncAttributeMaxDynamicSharedMemorySize, SMEM_SCORES);

    qkv_kernel    <<<dim3(6,16,3),  256>>>(hidden, Wq,bq, Wk,bk, Wv,bv);
    qw_kernel     <<<dim3(8,24,5),  256, 50176>>>(ssw);
    scores_kernel <<<dim3(24,8,8),  256, SMEM_SCORES>>>(mask, structm, dist, abv);
    softmax_kernel<<<3072,          256>>>();
    pv_kernel     <<<dim3(8,24),    256>>>(out);
}

// round 3
// speedup vs baseline: 1.4812x; 1.0146x over previous
#include <cuda_runtime.h>

#define BB  2
#define LL  1024
#define DD  768
#define HH  12
#define DHD 64
#define BHN (BB*HH)

// ---- scratch (device globals: allowed; no runtime allocation) ----
__device__ float g_q [BHN*LL*DHD];         //  6.3 MB  [bh][l][dh]
__device__ float g_k [BHN*LL*DHD];
__device__ float g_v [BHN*LL*DHD];
__device__ float g_qw[5*BHN*LL*DHD];       // 31.5 MB  [i][bh][l][dh]
__device__ float g_s [(size_t)BHN*LL*LL];  // 100.7 MB [bh][l][r]

// ============================================================
// tf32 helpers
// ============================================================
__device__ __forceinline__ unsigned f2tf(float x) {
    unsigned u; asm("cvt.rna.tf32.f32 %0, %1;" : "=r"(u) : "f"(x)); return u;
}

__device__ __forceinline__ void mma8(float* c, const uint4 a, const uint2 b) {
    asm volatile(
        "mma.sync.aligned.m16n8k8.row.col.f32.tf32.tf32.f32 "
        "{%0,%1,%2,%3}, {%4,%5,%6,%7}, {%8,%9}, {%0,%1,%2,%3};"
        : "+f"(c[0]), "+f"(c[1]), "+f"(c[2]), "+f"(c[3])
        : "r"(a.x), "r"(a.y), "r"(a.z), "r"(a.w), "r"(b.x), "r"(b.y));
}

// Stage a 128x64 row-major fp32 tile (row stride ld) into A-fragment tf32 SMEM.
// Layout: Af[ks(8)][mt(8)][lane(32)][4 regs] -> 8192 u32 = 32KB
__device__ __forceinline__ void stageA(unsigned* dst, const float* __restrict__ src,
                                       int ld, int tid) {
    #pragma unroll
    for (int it = 0; it < 8; it++) {
        int idx = tid + it*256;
        int m = idx >> 4, k4 = idx & 15;
        float4 v = *(const float4*)(src + (size_t)m*ld + k4*4);
        int mt = m >> 4, r = m & 15;
        int rbit = (r >> 3) & 1;
        int laneb = (r & 7) << 2;
        float vv[4] = {v.x, v.y, v.z, v.w};
        #pragma unroll
        for (int c2 = 0; c2 < 4; c2++) {
            int k  = k4*4 + c2;
            int ks = k >> 3, cc = k & 3, hf = (k >> 2) & 1;
            dst[((ks*8 + mt)*32 + (laneb | cc))*4 + (rbit + hf*2)] = f2tf(vv[c2]);
        }
    }
}

// Stage a 128(n)x64(k) n-major fp32 tile (row stride 64) into B-fragment tf32 SMEM.
// Layout: Bf[ks(8)][nt(16)][lane(32)][2 regs] -> 8192 u32 = 32KB. n>=nvalid zero.
__device__ __forceinline__ void stageB(unsigned* dst, const float* __restrict__ src,
                                       int tid, int nvalid) {
    #pragma unroll
    for (int it = 0; it < 8; it++) {
        int idx = tid + it*256;
        int n = idx >> 4, k4 = idx & 15;
        float4 v = make_float4(0.f, 0.f, 0.f, 0.f);
        if (n < nvalid) v = *(const float4*)(src + n*64 + k4*4);
        int nt = n >> 3;
        int laneb = (n & 7) << 2;
        float vv[4] = {v.x, v.y, v.z, v.w};
        #pragma unroll
        for (int c2 = 0; c2 < 4; c2++) {
            int k  = k4*4 + c2;
            int ks = k >> 3, cc = k & 3, hf = (k >> 2) & 1;
            dst[((ks*16 + nt)*32 + (laneb | cc))*2 + hf] = f2tf(vv[c2]);
        }
    }
}

// Stage a 64(k) x N(n) k-major fp32 tile (row stride ldn) into B-fragment layout
// (transposing). NT = N/8 n-tiles. For W / ssan_w / v operands.
template<int N>
__device__ __forceinline__ void stageBT(unsigned* dst, const float* __restrict__ src,
                                        int ldn, int tid) {
    constexpr int NT = N / 8;
    constexpr int F4 = N / 4;       // float4 per k-row
    #pragma unroll
    for (int it = 0; it < 64*F4/256; it++) {
        int idx = tid + it*256;
        int k = idx / F4, nq = idx % F4;
        float4 v = *(const float4*)(src + (size_t)k*ldn + nq*4);
        int ks = k >> 3, cc = k & 3, hf = (k >> 2) & 1;
        float vv[4] = {v.x, v.y, v.z, v.w};
        #pragma unroll
        for (int c2 = 0; c2 < 4; c2++) {
            int n = nq*4 + c2;
            int nt = n >> 3, laneb = (n & 7) << 2;
            dst[((ks*NT + nt)*32 + (laneb | cc))*2 + hf] = f2tf(vv[c2]);
        }
    }
}

// 128x128x64 GEMM pass: warp tile 32x64 (warp grid 4m x 2n).
__device__ __forceinline__ void gemm64(const unsigned* __restrict__ Af,
                                       const unsigned* __restrict__ Bf,
                                       int wm, int wn, int lane, float bacc[2][8][4]) {
    #pragma unroll
    for (int ks = 0; ks < 8; ks++) {
        uint4 a0 = *(const uint4*)(Af + ((ks*8 + wm*2 + 0)*32 + lane)*4);
        uint4 a1 = *(const uint4*)(Af + ((ks*8 + wm*2 + 1)*32 + lane)*4);
        #pragma unroll
        for (int j = 0; j < 8; j++) {
            uint2 b = *(const uint2*)(Bf + ((ks*16 + wn*8 + j)*32 + lane)*2);
            mma8(bacc[0][j], a0, b);
            mma8(bacc[1][j], a1, b);
        }
    }
}

// 128x64x64 GEMM pass: 8 warps, warp wid owns 16-row group wid. acc[8][4].
__device__ __forceinline__ void gemm64n64(const unsigned* __restrict__ Af,
                                          const unsigned* __restrict__ Bf,
                                          int wid, int lane, float acc[8][4]) {
    #pragma unroll
    for (int ks = 0; ks < 8; ks++) {
        uint4 a = *(const uint4*)(Af + ((ks*8 + wid)*32 + lane)*4);
        #pragma unroll
        for (int j = 0; j < 8; j++) {
            uint2 b = *(const uint2*)(Bf + ((ks*8 + j)*32 + lane)*2);
            mma8(acc[j], a, b);
        }
    }
}

__device__ __forceinline__ void zeroacc(float a[2][8][4]) {
    #pragma unroll
    for (int i = 0; i < 2; i++)
        #pragma unroll
        for (int j = 0; j < 8; j++)
            #pragma unroll
            for (int c = 0; c < 4; c++) a[i][j][c] = 0.f;
}

// Write bacc (c-fragment layout) into buf[128][132] fp32.
__device__ __forceinline__ void writeQE(float* buf, const float bacc[2][8][4],
                                        int wm, int wn, int lane) {
    int r0 = wm*32 + (lane >> 2);
    int c0 = wn*64 + (lane & 3)*2;
    #pragma unroll
    for (int i = 0; i < 2; i++)
        #pragma unroll
        for (int j = 0; j < 8; j++) {
            int rr = r0 + i*16, cc = c0 + j*8;
            *(float2*)(buf + rr*132 + cc)      = make_float2(bacc[i][j][0], bacc[i][j][1]);
            *(float2*)(buf + (rr+8)*132 + cc)  = make_float2(bacc[i][j][2], bacc[i][j][3]);
        }
}

__device__ __forceinline__ void gatherDiag(const float* __restrict__ buf, float acc[2][8][4],
                                           int wm, int wn, int lane, int half, bool useCol) {
    int r0 = wm*32 + (lane >> 2);
    int c0 = wn*64 + (lane & 3)*2;
    int off = 127 - half*128;
    #pragma unroll
    for (int i = 0; i < 2; i++)
        #pragma unroll
        for (int j = 0; j < 8; j++) {
            int rr = r0 + i*16, cc = c0 + j*8;
            #pragma unroll
            for (int c2 = 0; c2 < 4; c2++) {
                int R = rr + (c2 >> 1)*8;
                int C = cc + (c2 & 1);
                int J = R - C + off;
                if ((unsigned)J < 128u) {
                    int rowi = useCol ? C : R;
                    acc[i][j][c2] += buf[rowi*132 + J];
                }
            }
        }
}

// ============================================================
// K1: QKV projection on tensor cores (tf32).
// Tile 128m x 128n, K=768 in 12 chunks of 64. smem 64KB.
// ============================================================
__global__ __launch_bounds__(256) void qkv_kernel(
    const float* __restrict__ hidden,
    const float* __restrict__ Wq, const float* __restrict__ bq,
    const float* __restrict__ Wk, const float* __restrict__ bk,
    const float* __restrict__ Wv, const float* __restrict__ bv)
{
    extern __shared__ unsigned smu[];
    unsigned* Af = smu;
    unsigned* Bf = smu + 8192;

    const int mat = blockIdx.z;
    const float* W    = (mat==0) ? Wq : (mat==1 ? Wk : Wv);
    const float* bias = (mat==0) ? bq : (mat==1 ? bk : bv);
    float* outp       = (mat==0) ? g_q : (mat==1 ? g_k : g_v);

    const int n0 = blockIdx.x * 128;
    const int m0 = blockIdx.y * 128;
    const int tid = threadIdx.x, lane = tid & 31, wid = tid >> 5;
    const int wm = wid & 3, wn = wid >> 2;

    float acc[2][8][4];
    zeroacc(acc);

    for (int kc0 = 0; kc0 < DD; kc0 += 64) {
        stageA(Af, hidden + (size_t)m0*DD + kc0, DD, tid);
        stageBT<128>(Bf, W + (size_t)kc0*DD + n0, DD, tid);
        __syncthreads();
        gemm64(Af, Bf, wm, wn, lane, acc);
        __syncthreads();
    }

    const int r0 = wm*32 + (lane >> 2);
    const int c0 = wn*64 + (lane & 3)*2;
    #pragma unroll
    for (int i = 0; i < 2; i++)
        #pragma unroll
        for (int j = 0; j < 8; j++) {
            int cc = c0 + j*8;
            int cg = n0 + cc;
            int h = cg >> 6, dh = cg & 63;
            float2 bb = *(const float2*)(bias + cg);
            #pragma unroll
            for (int half = 0; half < 2; half++) {
                int rg = m0 + r0 + i*16 + half*8;
                int b = rg >> 10, l = rg & 1023;
                float2 v = make_float2(acc[i][j][half*2+0] + bb.x,
                                       acc[i][j][half*2+1] + bb.y);
                *(float2*)&outp[((b*HH + h)*LL + l)*DHD + dh] = v;
            }
        }
}

// ============================================================
// K1b: qw = q @ ssan_w[i][h] on tensor cores. Tile 128x64, K=64.
// smem 48KB.
// ============================================================
__global__ __launch_bounds__(256) void qw_kernel(const float* __restrict__ ssw)
{
    extern __shared__ unsigned smu[];
    unsigned* Af = smu;
    unsigned* Bf = smu + 8192;

    const int i5 = blockIdx.z;
    const int bh = blockIdx.y;
    const int h  = bh % HH;
    const int m0 = blockIdx.x * 128;
    const int tid = threadIdx.x, lane = tid & 31, wid = tid >> 5;

    stageA(Af, g_q + (bh*LL + m0)*DHD, DHD, tid);
    stageBT<64>(Bf, ssw + (size_t)(i5*HH + h)*DHD*DHD, DHD, tid);
    __syncthreads();

    float acc[8][4];
    #pragma unroll
    for (int j = 0; j < 8; j++)
        #pragma unroll
        for (int c = 0; c < 4; c++) acc[j][c] = 0.f;

    gemm64n64(Af, Bf, wid, lane, acc);

    float* ob = g_qw + ((size_t)(i5*BHN + bh)*LL + m0)*DHD;
    const int r0 = wid*16 + (lane >> 2);
    const int c0 = (lane & 3)*2;
    #pragma unroll
    for (int j = 0; j < 8; j++) {
        int cc = c0 + j*8;
        *(float2*)(ob + (size_t)r0*DHD + cc)     = make_float2(acc[j][0], acc[j][1]);
        *(float2*)(ob + (size_t)(r0+8)*DHD + cc) = make_float2(acc[j][2], acc[j][3]);
    }
}

// ============================================================
// K2: fused score kernel on tensor cores (unchanged from R2).
// ============================================================
#define SMEM_SCORES (49664*4)

__global__ __launch_bounds__(256, 1) void scores_kernel(
    const float* __restrict__ mask,
    const float* __restrict__ structm,
    const float* __restrict__ dist,
    const float* __restrict__ abv)
{
    extern __shared__ unsigned smu[];
    unsigned* Af   = smu;
    unsigned* KfB  = smu + 8192;
    unsigned* KaA  = smu + 16384;
    unsigned* Ef   = smu + 24576;
    float*    QEb  = (float*)(smu + 32768);   // 128*132 floats

    const int bh = blockIdx.x, kt = blockIdx.y, qt = blockIdx.z;
    const int b = bh / HH, h = bh % HH;
    const int m0 = qt*128, n0 = kt*128;
    const int tid = threadIdx.x, lane = tid & 31, wid = tid >> 5;
    const int wm = wid & 3, wn = wid >> 2;

    const float* qtile = g_q + (bh*LL + m0)*DHD;
    const float* ktile = g_k + (bh*LL + n0)*DHD;

    stageA(Af, qtile, DHD, tid);
    stageB(KfB, ktile, tid, 128);
    stageA(KaA, ktile, DHD, tid);
    const int base = (qt - kt)*128 + 896;
    stageB(Ef, dist + (size_t)base*DHD, tid, 128);
    __syncthreads();

    float acc[2][8][4];
    float bacc[2][8][4];
    zeroacc(acc);

    // positional half 0
    zeroacc(bacc);
    gemm64(Af, Ef, wm, wn, lane, bacc);
    writeQE(QEb, bacc, wm, wn, lane);
    __syncthreads();
    gatherDiag(QEb, acc, wm, wn, lane, 0, false);
    __syncthreads();

    zeroacc(bacc);
    gemm64(KaA, Ef, wm, wn, lane, bacc);
    writeQE(QEb, bacc, wm, wn, lane);
    __syncthreads();
    gatherDiag(QEb, acc, wm, wn, lane, 0, true);
    __syncthreads();

    // positional half 1
    {
        int nv = 1919 - base; if (nv > 128) nv = 128;
        stageB(Ef, dist + (size_t)(base + 128)*DHD, tid, nv);
    }
    __syncthreads();

    zeroacc(bacc);
    gemm64(Af, Ef, wm, wn, lane, bacc);
    writeQE(QEb, bacc, wm, wn, lane);
    __syncthreads();
    gatherDiag(QEb, acc, wm, wn, lane, 1, false);
    __syncthreads();

    zeroacc(bacc);
    gemm64(KaA, Ef, wm, wn, lane, bacc);
    writeQE(QEb, bacc, wm, wn, lane);
    __syncthreads();
    gatherDiag(QEb, acc, wm, wn, lane, 1, true);

    // q @ k^T, scale + mask
    zeroacc(bacc);
    gemm64(Af, KfB, wm, wn, lane, bacc);

    const float* mrow = mask + b*LL + n0;
    const int c0col = wn*64 + (lane & 3)*2;
    #pragma unroll
    for (int j = 0; j < 8; j++) {
        float2 mk = *(const float2*)(mrow + c0col + j*8);
        #pragma unroll
        for (int i = 0; i < 2; i++) {
            acc[i][j][0] = (acc[i][j][0] + bacc[i][j][0])*0.125f + mk.x;
            acc[i][j][1] = (acc[i][j][1] + bacc[i][j][1])*0.125f + mk.y;
            acc[i][j][2] = (acc[i][j][2] + bacc[i][j][2])*0.125f + mk.x;
            acc[i][j][3] = (acc[i][j][3] + bacc[i][j][3])*0.125f + mk.y;
        }
    }

    // 5 bilinear structure passes
    const int r0 = wm*32 + (lane >> 2);
    for (int i5 = 0; i5 < 5; i5++) {
        __syncthreads();
        stageA(Af, g_qw + (((size_t)i5*BHN + bh)*LL + m0)*DHD, DHD, tid);
        __syncthreads();
        zeroacc(bacc);
        gemm64(Af, KfB, wm, wn, lane, bacc);

        float ab = __ldg(&abv[i5*HH + h]);
        const float* stb = structm + (((size_t)(i5*BB + b)*LL + m0)*LL) + n0;
        #pragma unroll
        for (int i = 0; i < 2; i++)
            #pragma unroll
            for (int j = 0; j < 8; j++) {
                int rr = r0 + i*16, cc = c0col + j*8;
                float2 s0 = *(const float2*)(stb + (size_t)rr*LL + cc);
                float2 s1 = *(const float2*)(stb + (size_t)(rr+8)*LL + cc);
                acc[i][j][0] += (bacc[i][j][0] + ab)*s0.x;
                acc[i][j][1] += (bacc[i][j][1] + ab)*s0.y;
                acc[i][j][2] += (bacc[i][j][2] + ab)*s1.x;
                acc[i][j][3] += (bacc[i][j][3] + ab)*s1.y;
            }
    }

    float* sp = g_s + ((size_t)bh*LL + m0)*LL + n0;
    #pragma unroll
    for (int i = 0; i < 2; i++)
        #pragma unroll
        for (int j = 0; j < 8; j++) {
            int rr = r0 + i*16, cc = c0col + j*8;
            *(float2*)(sp + (size_t)rr*LL + cc)     = make_float2(acc[i][j][0], acc[i][j][1]);
            *(float2*)(sp + (size_t)(rr+8)*LL + cc) = make_float2(acc[i][j][2], acc[i][j][3]);
        }
}

// ============================================================
// K3: softmax (unchanged).
// ============================================================
__global__ __launch_bounds__(256) void softmax_kernel()
{
    const int warp = threadIdx.x >> 5, lane = threadIdx.x & 31;
    const size_t row = (size_t)blockIdx.x * 8 + warp;
    float* rp = g_s + row * LL;

    float4 v[8];
    float mx = -1e30f;
    #pragma unroll
    for (int k2 = 0; k2 < 8; k2++) {
        v[k2] = *(const float4*)&rp[(lane + k2*32)*4];
        mx = fmaxf(mx, fmaxf(fmaxf(v[k2].x, v[k2].y), fmaxf(v[k2].z, v[k2].w)));
    }
    #pragma unroll
    for (int o = 16; o > 0; o >>= 1) mx = fmaxf(mx, __shfl_xor_sync(0xffffffffu, mx, o));

    float s = 0.f;
    #pragma unroll
    for (int k2 = 0; k2 < 8; k2++) {
        v[k2].x = __expf(v[k2].x - mx);
        v[k2].y = __expf(v[k2].y - mx);
        v[k2].z = __expf(v[k2].z - mx);
        v[k2].w = __expf(v[k2].w - mx);
        s += v[k2].x + v[k2].y + v[k2].z + v[k2].w;
    }
    #pragma unroll
    for (int o = 16; o > 0; o >>= 1) s += __shfl_xor_sync(0xffffffffu, s, o);

    const float inv = 1.f / s;
    #pragma unroll
    for (int k2 = 0; k2 < 8; k2++) {
        v[k2].x *= inv; v[k2].y *= inv; v[k2].z *= inv; v[k2].w *= inv;
        *(float4*)&rp[(lane + k2*32)*4] = v[k2];
    }
}

// ============================================================
// K4: ctx = probs @ v on tensor cores (tf32). Tile 128x64,
// K=1024 in 16 chunks. smem 48KB.
// ============================================================
__global__ __launch_bounds__(256) void pv_kernel(float* __restrict__ out)
{
    extern __shared__ unsigned smu[];
    unsigned* Af = smu;
    unsigned* Bf = smu + 8192;

    const int bh = blockIdx.y;
    const int b = bh / HH, h = bh % HH;
    const int m0 = blockIdx.x * 128;
    const int tid = threadIdx.x, lane = tid & 31, wid = tid >> 5;

    const float* pb = g_s + (size_t)bh*LL*LL + (size_t)m0*LL;
    const float* vb = g_v + (size_t)bh*LL*DHD;

    float acc[8][4];
    #pragma unroll
    for (int j = 0; j < 8; j++)
        #pragma unroll
        for (int c = 0; c < 4; c++) acc[j][c] = 0.f;

    for (int kc0 = 0; kc0 < LL; kc0 += 64) {
        stageA(Af, pb + kc0, LL, tid);
        stageBT<64>(Bf, vb + (size_t)kc0*DHD, DHD, tid);
        __syncthreads();
        gemm64n64(Af, Bf, wid, lane, acc);
        __syncthreads();
    }

    const int r0 = wid*16 + (lane >> 2);
    const int c0 = (lane & 3)*2;
    #pragma unroll
    for (int j = 0; j < 8; j++) {
        int cc = c0 + j*8;
        #pragma unroll
        for (int half = 0; half < 2; half++) {
            int l = m0 + r0 + half*8;
            *(float2*)&out[((size_t)b*LL + l)*DD + h*DHD + cc] =
                make_float2(acc[j][half*2+0], acc[j][half*2+1]);
        }
    }
}

// ============================================================
extern "C" void kernel_launch(void* const* d_in, const int* in_sizes, int n_in,
                              void* d_out, int out_size)
{
    const float* hidden  = (const float*)d_in[0];
    const float* mask    = (const float*)d_in[1];
    const float* structm = (const float*)d_in[2];
    const float* Wq      = (const float*)d_in[3];
    const float* bq      = (const float*)d_in[4];
    const float* Wk      = (const float*)d_in[5];
    const float* bk      = (const float*)d_in[6];
    const float* Wv      = (const float*)d_in[7];
    const float* bv      = (const float*)d_in[8];
    const float* dist    = (const float*)d_in[9];
    const float* ssw     = (const float*)d_in[10];
    const float* abv     = (const float*)d_in[11];
    float* out = (float*)d_out;

    cudaFuncSetAttribute(qkv_kernel,    cudaFuncAttributeMaxDynamicSharedMemorySize, 65536);
    cudaFuncSetAttribute(qw_kernel,     cudaFuncAttributeMaxDynamicSharedMemorySize, 49152);
    cudaFuncSetAttribute(pv_kernel,     cudaFuncAttributeMaxDynamicSharedMemorySize, 49152);
    cudaFuncSetAttribute(scores_kernel, cudaFuncAttributeMaxDynamicSharedMemorySize, SMEM_SCORES);

    qkv_kernel    <<<dim3(6,16,3),  256, 65536>>>(hidden, Wq,bq, Wk,bk, Wv,bv);
    qw_kernel     <<<dim3(8,24,5),  256, 49152>>>(ssw);
    scores_kernel <<<dim3(24,8,8),  256, SMEM_SCORES>>>(mask, structm, dist, abv);
    softmax_kernel<<<3072,          256>>>();
    pv_kernel     <<<dim3(8,24),    256, 49152>>>(out);
}